// round 1
// baseline (speedup 1.0000x reference)
#include <cuda_runtime.h>
#include <stdint.h>

// Problem constants
#define BATCH 8192
#define DIM   2048
#define UNITS 2048
#define KW    (DIM / 32)   // 64 packed words along D

// Block tiling for the binary GEMM
#define BM 64
#define BN 64
#define NTHREADS 256

// Scratch: packed sign bits (bit = 1 iff value >= 0)
__device__ uint32_t g_xbits[(size_t)BATCH * KW];   // 2 MB
__device__ uint32_t g_kbits[(size_t)UNITS * KW];   // 0.5 MB  (column-major over D: [unit][word])

// ---------------------------------------------------------------------------
// Pack inputs [BATCH, DIM] fp32 -> bit rows. One thread per element; warp
// ballot forms the 32-bit word. Fully coalesced reads, 1 store per warp.
// ---------------------------------------------------------------------------
__global__ void pack_x_kernel(const float* __restrict__ x) {
    int idx = blockIdx.x * blockDim.x + threadIdx.x;      // element index
    float v = x[idx];
    unsigned m = __ballot_sync(0xffffffffu, v >= 0.0f);
    if ((threadIdx.x & 31) == 0) {
        g_xbits[idx >> 5] = m;
    }
}

// ---------------------------------------------------------------------------
// Pack kernel [DIM, UNITS] fp32 -> per-unit bit columns g_kbits[n*KW + w],
// bit j of word w = sign(kernel[(w*32+j)*UNITS + n]).
// blockIdx.x = w (0..KW-1), blockIdx.y picks a 256-wide slab of n.
// Each inner read is coalesced across n.
// ---------------------------------------------------------------------------
__global__ void pack_k_kernel(const float* __restrict__ k) {
    int w = blockIdx.x;
    int n = blockIdx.y * blockDim.x + threadIdx.x;
    const float* col = k + (size_t)w * 32 * UNITS + n;
    uint32_t bits = 0;
#pragma unroll
    for (int j = 0; j < 32; ++j) {
        bits |= (col[(size_t)j * UNITS] >= 0.0f ? 1u : 0u) << j;
    }
    g_kbits[(size_t)n * KW + w] = bits;
}

// ---------------------------------------------------------------------------
// Binary GEMM: out[r][c] = DIM - 2*popc(xrow ^ kcol) + bias[c]
//
// 256 threads, BM=BN=64, each thread computes a 4x4 tile of outputs at
// rows (tm + 16*i), cols (tn + 16*j), tm = tid>>4, tn = tid&15.
//
// Shared tiles are stored WORD-major with an XOR swizzle on the low 5 bits
// of the row index: element (w, r) lives at [w*64 + (r ^ (w & 31))].
//  - Loader: lanes have consecutive w, fixed r  -> banks (r^w)%32 distinct.
//  - Compute: lanes have fixed w, distinct r    -> banks distinct/broadcast.
// Both directions conflict-free.
// ---------------------------------------------------------------------------
__global__ __launch_bounds__(NTHREADS)
void bgemm_kernel(const float* __restrict__ bias, float* __restrict__ out) {
    __shared__ uint32_t sa[KW * BM];
    __shared__ uint32_t sb[KW * BN];

    const int tid  = threadIdx.x;
    const int row0 = blockIdx.y * BM;
    const int col0 = blockIdx.x * BN;

    // Cooperative load of 64x64-word A and B tiles (whole K dimension).
    {
        const int w  = tid & 63;        // word index 0..63
        const int r0 = tid >> 6;        // 0..3
        const int s  = w & 31;
#pragma unroll
        for (int it = 0; it < 16; ++it) {
            const int r = r0 + it * 4;
            sa[w * BM + (r ^ s)] = g_xbits[(size_t)(row0 + r) * KW + w];
            sb[w * BN + (r ^ s)] = g_kbits[(size_t)(col0 + r) * KW + w];
        }
    }
    __syncthreads();

    const int tm = tid >> 4;   // 0..15
    const int tn = tid & 15;   // 0..15

    int acc[4][4];
#pragma unroll
    for (int i = 0; i < 4; ++i)
#pragma unroll
        for (int j = 0; j < 4; ++j) acc[i][j] = 0;

#pragma unroll 8
    for (int w = 0; w < KW; ++w) {
        const int s = w & 31;
        uint32_t a[4], b[4];
#pragma unroll
        for (int i = 0; i < 4; ++i) a[i] = sa[w * BM + ((tm + 16 * i) ^ s)];
#pragma unroll
        for (int j = 0; j < 4; ++j) b[j] = sb[w * BN + ((tn + 16 * j) ^ s)];
#pragma unroll
        for (int i = 0; i < 4; ++i)
#pragma unroll
            for (int j = 0; j < 4; ++j)
                acc[i][j] += __popc(a[i] ^ b[j]);
    }

#pragma unroll
    for (int i = 0; i < 4; ++i) {
        const int r = row0 + tm + 16 * i;
#pragma unroll
        for (int j = 0; j < 4; ++j) {
            const int c = col0 + tn + 16 * j;
            out[(size_t)r * UNITS + c] = (float)(DIM - 2 * acc[i][j]) + bias[c];
        }
    }
}

// ---------------------------------------------------------------------------
// Harness entry. Inputs (metadata order): inputs[B,D] f32, kernel[D,U] f32,
// bias[U] f32. Output: [B,U] f32.
// ---------------------------------------------------------------------------
extern "C" void kernel_launch(void* const* d_in, const int* in_sizes, int n_in,
                              void* d_out, int out_size) {
    (void)in_sizes; (void)n_in; (void)out_size;
    const float* x    = (const float*)d_in[0];
    const float* k    = (const float*)d_in[1];
    const float* bias = (const float*)d_in[2];
    float* out        = (float*)d_out;

    pack_x_kernel<<<(BATCH * DIM) / 256, 256>>>(x);
    pack_k_kernel<<<dim3(KW, UNITS / 256), 256>>>(k);
    bgemm_kernel<<<dim3(UNITS / BN, BATCH / BM), NTHREADS>>>(bias, out);
}